// round 1
// baseline (speedup 1.0000x reference)
#include <cuda_runtime.h>
#include <cuda_bf16.h>
#include <cstdint>

// Problem constants
constexpr int NN = 50000;    // nodes
constexpr int NE = 800000;   // edges
constexpr int NG = 1024;     // graphs
constexpr int H  = 128;      // hidden / node feature dim
constexpr int DS = 768;      // smiles dim
constexpr int NC = 12;       // classes

// Scratch (device globals; no allocation allowed)
__device__ float g_bufA[(size_t)NN * H];
__device__ float g_bufB[(size_t)NN * H];
__device__ float g_dinv[NN];
__device__ int   g_deg[NN];
__device__ float g_gsum[NG * H];
__device__ int   g_cnt[NG];

// ---------------------------------------------------------------------------
// Vectorized no-return atomic add (sm_90+)
// ---------------------------------------------------------------------------
__device__ __forceinline__ void red_add_v4(float* p, float4 v) {
    asm volatile("red.global.add.v4.f32 [%0], {%1, %2, %3, %4};"
                 :: "l"(p), "f"(v.x), "f"(v.y), "f"(v.z), "f"(v.w)
                 : "memory");
}

// ---------------------------------------------------------------------------
// K0: zero/init counters. Covers max(NN, NG*H).
// ---------------------------------------------------------------------------
__global__ void prep_zero_kernel(int* __restrict__ deg, int* __restrict__ cnt,
                                 float* __restrict__ gsum) {
    int i = blockIdx.x * blockDim.x + threadIdx.x;
    if (i < NN) deg[i] = 1;            // self-loop contributes 1 to degree
    if (i < NG) cnt[i] = 0;
    if (i < NG * H) gsum[i] = 0.0f;
}

// ---------------------------------------------------------------------------
// K1: degree count over edges (dst) + node counts per graph. Grid covers NE.
// ---------------------------------------------------------------------------
__global__ void count_kernel(const int* __restrict__ dst, const int* __restrict__ batch,
                             int* __restrict__ deg, int* __restrict__ cnt) {
    int i = blockIdx.x * blockDim.x + threadIdx.x;
    if (i < NE) atomicAdd(&deg[dst[i]], 1);
    if (i < NN) atomicAdd(&cnt[batch[i]], 1);
}

// ---------------------------------------------------------------------------
// K2: dinv = rsqrt(deg)
// ---------------------------------------------------------------------------
__global__ void dinv_kernel(const int* __restrict__ deg, float* __restrict__ dinv) {
    int i = blockIdx.x * blockDim.x + threadIdx.x;
    if (i < NN) dinv[i] = rsqrtf((float)deg[i]);
}

// ---------------------------------------------------------------------------
// K3/K6: GEMM  Out[M,128] = (reluIn ? relu(A) : A)[M,128] @ W[128,128]
// BM=64, BK=32, 256 threads, each thread computes 4 rows x 8 cols.
// ---------------------------------------------------------------------------
__global__ __launch_bounds__(256)
void gemm128_kernel(const float* __restrict__ A, const float* __restrict__ W,
                    float* __restrict__ Out, int M, int reluIn) {
    __shared__ float  Xs[64][33];          // padded to kill bank conflicts
    __shared__ float4 Ws[32][32];          // 32 k-rows x 128 cols (as float4)

    const int tid = threadIdx.x;
    const int tx  = tid & 15;              // 0..15 -> col group (8 cols each)
    const int ty  = tid >> 4;              // 0..15 -> row within 16-row stripe
    const int row0 = blockIdx.x * 64;

    float acc[4][8];
#pragma unroll
    for (int mi = 0; mi < 4; mi++)
#pragma unroll
        for (int n = 0; n < 8; n++) acc[mi][n] = 0.0f;

    for (int k0 = 0; k0 < 128; k0 += 32) {
        // Load X tile: 64 rows x 32 cols = 512 float4s, 2 per thread.
#pragma unroll
        for (int i = 0; i < 2; i++) {
            int li = tid + i * 256;        // 0..511
            int r  = li >> 3;              // row 0..63
            int c4 = li & 7;               // float4 col 0..7
            int gr = row0 + r;
            float4 v = make_float4(0.f, 0.f, 0.f, 0.f);
            if (gr < M)
                v = __ldg((const float4*)(A + (size_t)gr * 128 + k0) + c4);
            if (reluIn) {
                v.x = fmaxf(v.x, 0.f); v.y = fmaxf(v.y, 0.f);
                v.z = fmaxf(v.z, 0.f); v.w = fmaxf(v.w, 0.f);
            }
            Xs[r][c4 * 4 + 0] = v.x; Xs[r][c4 * 4 + 1] = v.y;
            Xs[r][c4 * 4 + 2] = v.z; Xs[r][c4 * 4 + 3] = v.w;
        }
        // Load W tile: 32 k-rows x 128 cols = 1024 float4s, 4 per thread.
#pragma unroll
        for (int i = 0; i < 4; i++) {
            int li = tid + i * 256;        // 0..1023
            int kr = li >> 5;              // 0..31
            int c4 = li & 31;              // 0..31
            Ws[kr][c4] = __ldg((const float4*)(W + (size_t)(k0 + kr) * 128) + c4);
        }
        __syncthreads();

#pragma unroll
        for (int kk = 0; kk < 32; kk++) {
            float xv[4];
#pragma unroll
            for (int mi = 0; mi < 4; mi++) xv[mi] = Xs[ty + 16 * mi][kk];
            float4 w0 = Ws[kk][tx * 2 + 0];
            float4 w1 = Ws[kk][tx * 2 + 1];
#pragma unroll
            for (int mi = 0; mi < 4; mi++) {
                acc[mi][0] += xv[mi] * w0.x;
                acc[mi][1] += xv[mi] * w0.y;
                acc[mi][2] += xv[mi] * w0.z;
                acc[mi][3] += xv[mi] * w0.w;
                acc[mi][4] += xv[mi] * w1.x;
                acc[mi][5] += xv[mi] * w1.y;
                acc[mi][6] += xv[mi] * w1.z;
                acc[mi][7] += xv[mi] * w1.w;
            }
        }
        __syncthreads();
    }

#pragma unroll
    for (int mi = 0; mi < 4; mi++) {
        int row = row0 + ty + 16 * mi;
        if (row < M) {
            float4* op = (float4*)(Out + (size_t)row * 128 + tx * 8);
            op[0] = make_float4(acc[mi][0], acc[mi][1], acc[mi][2], acc[mi][3]);
            op[1] = make_float4(acc[mi][4], acc[mi][5], acc[mi][6], acc[mi][7]);
        }
    }
}

// ---------------------------------------------------------------------------
// K4/K7: init agg buffer with bias + self-loop term:
//   agg[i,:] = bias[:] + h[i,:] * dinv[i]^2
// One float4 per thread; grid covers NN*32 float4s.
// ---------------------------------------------------------------------------
__global__ void init_agg_kernel(const float* __restrict__ h, const float* __restrict__ dinv,
                                const float* __restrict__ bias, float* __restrict__ agg) {
    int v = blockIdx.x * blockDim.x + threadIdx.x;
    if (v >= NN * 32) return;
    int row = v >> 5;
    int c4  = v & 31;
    float di = dinv[row];
    float d2 = di * di;
    float4 hv = __ldg((const float4*)h + v);
    float4 bv = __ldg((const float4*)bias + c4);
    float4 o;
    o.x = bv.x + hv.x * d2; o.y = bv.y + hv.y * d2;
    o.z = bv.z + hv.z * d2; o.w = bv.w + hv.w * d2;
    ((float4*)agg)[v] = o;
}

// ---------------------------------------------------------------------------
// K5/K8: edge aggregation. One warp per edge, one float4 per lane.
//   agg[dst,:] += h[src,:] * dinv[src]*dinv[dst]
// ---------------------------------------------------------------------------
__global__ __launch_bounds__(256)
void edge_kernel(const int* __restrict__ src, const int* __restrict__ dst,
                 const float* __restrict__ dinv, const float* __restrict__ h,
                 float* __restrict__ agg) {
    int g = blockIdx.x * blockDim.x + threadIdx.x;
    int e = g >> 5;
    if (e >= NE) return;
    int lane = g & 31;
    int s = __ldg(&src[e]);
    int d = __ldg(&dst[e]);
    float w = __ldg(&dinv[s]) * __ldg(&dinv[d]);
    float4 v = __ldg((const float4*)(h + (size_t)s * 128) + lane);
    v.x *= w; v.y *= w; v.z *= w; v.w *= w;
    red_add_v4(agg + (size_t)d * 128 + (size_t)lane * 4, v);
}

// ---------------------------------------------------------------------------
// K9: pooling. One warp per node: gsum[batch[i],:] += relu(h[i,:])
// ---------------------------------------------------------------------------
__global__ __launch_bounds__(256)
void pool_kernel(const float* __restrict__ h, const int* __restrict__ batch,
                 float* __restrict__ gsum) {
    int g = blockIdx.x * blockDim.x + threadIdx.x;
    int node = g >> 5;
    if (node >= NN) return;
    int lane = g & 31;
    int b = __ldg(&batch[node]);
    float4 v = __ldg((const float4*)(h + (size_t)node * 128) + lane);
    v.x = fmaxf(v.x, 0.f); v.y = fmaxf(v.y, 0.f);
    v.z = fmaxf(v.z, 0.f); v.w = fmaxf(v.w, 0.f);
    red_add_v4(gsum + (size_t)b * 128 + (size_t)lane * 4, v);
}

// ---------------------------------------------------------------------------
// K10: per-graph fused head. 1 block = 1 graph, 128 threads.
//   s  = relu(smiles @ Ws1 + bs1) @ Ws2 + bs2
//   g  = gsum / max(cnt,1)
//   f  = relu([s, g] @ Wf + bf)
//   out = f @ Wo + bo
// ---------------------------------------------------------------------------
__global__ __launch_bounds__(128)
void final_kernel(const float* __restrict__ smiles,
                  const float* __restrict__ Ws1, const float* __restrict__ bs1,
                  const float* __restrict__ Ws2, const float* __restrict__ bs2,
                  const float* __restrict__ Wf,  const float* __restrict__ bf,
                  const float* __restrict__ Wo,  const float* __restrict__ bo,
                  const float* __restrict__ gsum, const int* __restrict__ cnt,
                  float* __restrict__ out) {
    __shared__ float sm[DS];
    __shared__ float s1[H];
    __shared__ float comb[2 * H];
    __shared__ float fused[H];

    const int b = blockIdx.x;
    const int j = threadIdx.x;

    for (int k = j; k < DS; k += H) sm[k] = __ldg(&smiles[(size_t)b * DS + k]);
    __syncthreads();

    // layer 1: [768] -> [128]
    {
        float a0 = 0.f, a1 = 0.f, a2 = 0.f, a3 = 0.f;
        for (int k = 0; k < DS; k += 4) {
            a0 += sm[k + 0] * __ldg(&Ws1[(size_t)(k + 0) * H + j]);
            a1 += sm[k + 1] * __ldg(&Ws1[(size_t)(k + 1) * H + j]);
            a2 += sm[k + 2] * __ldg(&Ws1[(size_t)(k + 2) * H + j]);
            a3 += sm[k + 3] * __ldg(&Ws1[(size_t)(k + 3) * H + j]);
        }
        s1[j] = fmaxf(__ldg(&bs1[j]) + a0 + a1 + a2 + a3, 0.f);
    }
    __syncthreads();

    // layer 2: [128] -> [128]; also fetch pooled g
    {
        float a0 = 0.f, a1 = 0.f, a2 = 0.f, a3 = 0.f;
        for (int k = 0; k < H; k += 4) {
            a0 += s1[k + 0] * __ldg(&Ws2[(size_t)(k + 0) * H + j]);
            a1 += s1[k + 1] * __ldg(&Ws2[(size_t)(k + 1) * H + j]);
            a2 += s1[k + 2] * __ldg(&Ws2[(size_t)(k + 2) * H + j]);
            a3 += s1[k + 3] * __ldg(&Ws2[(size_t)(k + 3) * H + j]);
        }
        comb[j] = __ldg(&bs2[j]) + a0 + a1 + a2 + a3;
        float c = (float)__ldg(&cnt[b]);
        comb[H + j] = __ldg(&gsum[(size_t)b * H + j]) / fmaxf(c, 1.f);
    }
    __syncthreads();

    // fusion: [256] -> [128]
    {
        float a0 = 0.f, a1 = 0.f, a2 = 0.f, a3 = 0.f;
        for (int k = 0; k < 2 * H; k += 4) {
            a0 += comb[k + 0] * __ldg(&Wf[(size_t)(k + 0) * H + j]);
            a1 += comb[k + 1] * __ldg(&Wf[(size_t)(k + 1) * H + j]);
            a2 += comb[k + 2] * __ldg(&Wf[(size_t)(k + 2) * H + j]);
            a3 += comb[k + 3] * __ldg(&Wf[(size_t)(k + 3) * H + j]);
        }
        fused[j] = fmaxf(__ldg(&bf[j]) + a0 + a1 + a2 + a3, 0.f);
    }
    __syncthreads();

    // output head: [128] -> [12]
    if (j < NC) {
        float a0 = 0.f, a1 = 0.f, a2 = 0.f, a3 = 0.f;
        for (int k = 0; k < H; k += 4) {
            a0 += fused[k + 0] * __ldg(&Wo[(size_t)(k + 0) * NC + j]);
            a1 += fused[k + 1] * __ldg(&Wo[(size_t)(k + 1) * NC + j]);
            a2 += fused[k + 2] * __ldg(&Wo[(size_t)(k + 2) * NC + j]);
            a3 += fused[k + 3] * __ldg(&Wo[(size_t)(k + 3) * NC + j]);
        }
        out[(size_t)b * NC + j] = __ldg(&bo[j]) + a0 + a1 + a2 + a3;
    }
}

// ---------------------------------------------------------------------------
extern "C" void kernel_launch(void* const* d_in, const int* in_sizes, int n_in,
                              void* d_out, int out_size) {
    const float* smiles = (const float*)d_in[0];
    const float* x      = (const float*)d_in[1];
    const int*   ei     = (const int*)d_in[2];
    const int*   batch  = (const int*)d_in[3];
    const float* Ws1 = (const float*)d_in[4];
    const float* bs1 = (const float*)d_in[5];
    const float* Ws2 = (const float*)d_in[6];
    const float* bs2 = (const float*)d_in[7];
    const float* Wg1 = (const float*)d_in[8];
    const float* bg1 = (const float*)d_in[9];
    const float* Wg2 = (const float*)d_in[10];
    const float* bg2 = (const float*)d_in[11];
    const float* Wf  = (const float*)d_in[12];
    const float* bf  = (const float*)d_in[13];
    const float* Wo  = (const float*)d_in[14];
    const float* bo  = (const float*)d_in[15];
    float* out = (float*)d_out;

    float *bufA, *bufB, *dinv, *gsum;
    int *deg, *cnt;
    cudaGetSymbolAddress((void**)&bufA, g_bufA);
    cudaGetSymbolAddress((void**)&bufB, g_bufB);
    cudaGetSymbolAddress((void**)&dinv, g_dinv);
    cudaGetSymbolAddress((void**)&deg,  g_deg);
    cudaGetSymbolAddress((void**)&gsum, g_gsum);
    cudaGetSymbolAddress((void**)&cnt,  g_cnt);

    const int* src = ei;
    const int* dst = ei + NE;

    const int T = 256;
    // init counters
    prep_zero_kernel<<<(NG * H + T - 1) / T, T>>>(deg, cnt, gsum);
    // degree + graph counts
    count_kernel<<<(NE + T - 1) / T, T>>>(dst, batch, deg, cnt);
    dinv_kernel<<<(NN + T - 1) / T, T>>>(deg, dinv);

    // --- GCN layer 1 ---
    gemm128_kernel<<<(NN + 63) / 64, 256>>>(x, Wg1, bufA, NN, 0);
    init_agg_kernel<<<(NN * 32 + T - 1) / T, T>>>(bufA, dinv, bg1, bufB);
    edge_kernel<<<(NE * 32 + T - 1) / T, T>>>(src, dst, dinv, bufA, bufB);

    // --- GCN layer 2 (relu applied on load of bufB) ---
    gemm128_kernel<<<(NN + 63) / 64, 256>>>(bufB, Wg2, bufA, NN, 1);
    init_agg_kernel<<<(NN * 32 + T - 1) / T, T>>>(bufA, dinv, bg2, bufB);
    edge_kernel<<<(NE * 32 + T - 1) / T, T>>>(src, dst, dinv, bufA, bufB);

    // --- mean pool (relu on load) ---
    pool_kernel<<<(NN * 32 + T - 1) / T, T>>>(bufB, batch, gsum);

    // --- SMILES MLP + fusion + output head ---
    final_kernel<<<NG, 128>>>(smiles, Ws1, bs1, Ws2, bs2, Wf, bf, Wo, bo,
                              gsum, cnt, out);
}